// round 8
// baseline (speedup 1.0000x reference)
#include <cuda_runtime.h>
#include <cuda_bf16.h>
#include <cstdint>

#define EE    256
#define HH    4
#define DH    64
#define BB    8
#define CC    32
#define RR    255
#define SS    256
#define HID   1024
#define NBC   (BB*CC)
#define TOK   8
#define NSL   16           // j-split slices (64 j each)
#define LN_EPS 1e-5f

// ---------------- device scratch ----------------
__device__ __align__(16) float g_u[HH*EE];
__device__ __align__(16) float g_cb[HH];
__device__ __align__(16) float g_bias2[EE];
__device__ __align__(16) float g_M2T[HID*EE];      // [j][f]
__device__ __align__(16) float g_W1T[EE*HID];      // [e][j]
__device__ __align__(16) float g_W2T[HID*EE];      // [j][f]
__device__ __align__(16) float g_xbar[NBC*HID];
__device__ __align__(16) float g_ln[NBC*EE];
__device__ __align__(16) float g_hid[NBC*HID];
__device__ __align__(16) float g_part[NSL*NBC*EE];   // 4MB
__device__ __align__(16) float g_part2[NSL*NBC*EE];  // 4MB
__device__ unsigned g_cnt1[NBC/TOK];                 // zero-init; self-reset
__device__ unsigned g_cnt2[NBC/TOK];

// ---------------- cp.async helpers ----------------
__device__ __forceinline__ void cp_async16(float* sdst, const float4* gsrc) {
    unsigned sa = (unsigned)__cvta_generic_to_shared(sdst);
    asm volatile("cp.async.ca.shared.global [%0], [%1], 16;" :: "r"(sa), "l"(gsrc));
}
__device__ __forceinline__ void cp_commit() { asm volatile("cp.async.commit_group;"); }
__device__ __forceinline__ void cp_wait1()  { asm volatile("cp.async.wait_group 1;"); }
__device__ __forceinline__ void cp_wait0()  { asm volatile("cp.async.wait_group 0;"); }

#define ACC8(m, tA, tB) do { \
    a[0].x += (m).x*(tA).x; a[0].y += (m).y*(tA).x; a[0].z += (m).z*(tA).x; a[0].w += (m).w*(tA).x; \
    a[1].x += (m).x*(tA).y; a[1].y += (m).y*(tA).y; a[1].z += (m).z*(tA).y; a[1].w += (m).w*(tA).y; \
    a[2].x += (m).x*(tA).z; a[2].y += (m).y*(tA).z; a[2].z += (m).z*(tA).z; a[2].w += (m).w*(tA).z; \
    a[3].x += (m).x*(tA).w; a[3].y += (m).y*(tA).w; a[3].z += (m).z*(tA).w; a[3].w += (m).w*(tA).w; \
    a[4].x += (m).x*(tB).x; a[4].y += (m).y*(tB).x; a[4].z += (m).z*(tB).x; a[4].w += (m).w*(tB).x; \
    a[5].x += (m).x*(tB).y; a[5].y += (m).y*(tB).y; a[5].z += (m).z*(tB).y; a[5].w += (m).w*(tB).y; \
    a[6].x += (m).x*(tB).z; a[6].y += (m).y*(tB).z; a[6].z += (m).z*(tB).z; a[6].w += (m).w*(tB).z; \
    a[7].x += (m).x*(tB).w; a[7].y += (m).y*(tB).w; a[7].z += (m).z*(tB).w; a[7].w += (m).w*(tB).w; \
} while(0)

__device__ __forceinline__ float blk_sum256(float v, volatile float* s8, int tid) {
    #pragma unroll
    for (int o = 16; o; o >>= 1) v += __shfl_xor_sync(0xffffffffu, v, o);
    if ((tid & 31) == 0) s8[tid >> 5] = v;
    __syncthreads();
    float r = s8[0]+s8[1]+s8[2]+s8[3]+s8[4]+s8[5]+s8[6]+s8[7];
    __syncthreads();
    return r;
}

// warp-cooperative dot of a gmem row with smem vector (256 elems)
__device__ __forceinline__ float warp_dot256(const float* __restrict__ row,
                                             const float* __restrict__ svec, int lane) {
    float4 w0 = *(const float4*)(row + lane*4);
    float4 w1 = *(const float4*)(row + 128 + lane*4);
    float4 c0 = *(const float4*)(svec + lane*4);
    float4 c1 = *(const float4*)(svec + 128 + lane*4);
    float acc = w0.x*c0.x + w0.y*c0.y + w0.z*c0.z + w0.w*c0.w
              + w1.x*c1.x + w1.y*c1.y + w1.z*c1.z + w1.w*c1.w;
    #pragma unroll
    for (int o = 16; o; o >>= 1) acc += __shfl_xor_sync(0xffffffffu, acc, o);
    return acc;
}

// ---------------- kernel: setup ----------------
// [0,64): M2T | [64,576): transposes | [576,584): u | 584: cb | [585,593): bias2
__global__ __launch_bounds__(256) void setup_kernel(const float* __restrict__ cls,
                              const float* __restrict__ w_qkv,
                              const float* __restrict__ b_qkv,
                              const float* __restrict__ w_out,
                              const float* __restrict__ b_out,
                              const float* __restrict__ w1,
                              const float* __restrict__ w2) {
    int bi = blockIdx.x;
    int tid = threadIdx.x;

    if (bi < 64) {
        __shared__ float sa[64][64];
        __shared__ float sb[64][65];
        int h = bi >> 4, e0 = ((bi >> 2) & 3) * 64, f0 = (bi & 3) * 64;
        for (int i = tid; i < 4096; i += 256) {
            int d = i >> 6, el = i & 63;
            sa[d][el] = w_qkv[(size_t)(2*EE + h*64 + d) * EE + e0 + el];
        }
        for (int i = tid; i < 4096; i += 256) {
            int fl = i >> 6, d = i & 63;
            sb[fl][d] = w_out[(size_t)(f0 + fl) * EE + h*64 + d];
        }
        __syncthreads();
        int tx = tid & 15, ty = tid >> 4;
        float acc[4][4] = {};
        #pragma unroll 4
        for (int d = 0; d < 64; d++) {
            float av[4], bv[4];
            #pragma unroll
            for (int i = 0; i < 4; i++) av[i] = sa[d][ty*4 + i];
            #pragma unroll
            for (int i = 0; i < 4; i++) bv[i] = sb[tx*4 + i][d];
            #pragma unroll
            for (int i = 0; i < 4; i++)
                #pragma unroll
                for (int j = 0; j < 4; j++) acc[i][j] += av[i] * bv[j];
        }
        #pragma unroll
        for (int i = 0; i < 4; i++)
            *(float4*)&g_M2T[(size_t)(h*256 + e0 + ty*4 + i) * EE + f0 + tx*4] = *(float4*)acc[i];
        return;
    }
    if (bi < 576) {
        __shared__ float s[32][33];
        int a = bi - 64;
        const float* src; float* dst; int rows, cols, bx, by;
        if (a < 256) {
            src = w1; dst = g_W1T; rows = HID; cols = EE;
            bx = (a & 7) * 32; by = (a >> 3) * 32;
        } else {
            a -= 256;
            src = w2; dst = g_W2T; rows = EE; cols = HID;
            bx = (a & 31) * 32; by = (a >> 5) * 32;
        }
        int tx = tid & 31, ty = tid >> 5;
        #pragma unroll
        for (int r = 0; r < 4; r++)
            s[ty + r*8][tx] = src[(size_t)(by + ty + r*8) * cols + bx + tx];
        __syncthreads();
        #pragma unroll
        for (int r = 0; r < 4; r++)
            dst[(size_t)(bx + ty + r*8) * rows + by + tx] = s[tx][ty + r*8];
        return;
    }
    if (bi < 584) {
        // u[h][e] for one (h, e-half). Computes its own q0 slice (64 rows) first.
        __shared__ float s_cls[EE];
        __shared__ float s_q[DH];
        __shared__ float s_p[2][128];
        int k = bi - 576;
        int h = k >> 1, e0 = (k & 1) * 128;
        int warp = tid >> 5, lane = tid & 31;
        if (tid < EE) s_cls[tid] = cls[tid];
        __syncthreads();
        #pragma unroll
        for (int r = 0; r < 8; r++) {
            int d = warp*8 + r;
            float acc = warp_dot256(w_qkv + (size_t)(h*DH + d) * EE, s_cls, lane);
            if (lane == 0) s_q[d] = acc + b_qkv[h*DH + d];
        }
        __syncthreads();
        int dg = tid >> 7, e = e0 + (tid & 127);
        float acc = 0.f;
        #pragma unroll 8
        for (int i = 0; i < 32; i++) {
            int d = dg*32 + i;
            acc += s_q[d] * w_qkv[(size_t)(EE + h*DH + d) * EE + e];
        }
        s_p[dg][tid & 127] = acc;
        __syncthreads();
        if (tid < 128)
            g_u[h*EE + e0 + tid] = 0.125f * (s_p[0][tid] + s_p[1][tid]);
        return;
    }
    if (bi == 584) {
        // cb[h] — computes full q0 locally
        __shared__ float s_cls[EE];
        __shared__ float s_q0[EE];
        __shared__ float s_w[8];
        int warp = tid >> 5, lane = tid & 31;
        if (tid < EE) s_cls[tid] = cls[tid];
        __syncthreads();
        for (int r = 0; r < 32; r++) {
            int row = warp*32 + r;
            float acc = warp_dot256(w_qkv + (size_t)row * EE, s_cls, lane);
            if (lane == 0) s_q0[row] = acc + b_qkv[row];
        }
        __syncthreads();
        float v = s_q0[tid] * b_qkv[EE + tid];
        #pragma unroll
        for (int o = 16; o; o >>= 1) v += __shfl_xor_sync(0xffffffffu, v, o);
        if ((tid & 31) == 0) s_w[tid >> 5] = v;
        __syncthreads();
        if (tid < HH) g_cb[tid] = 0.125f * (s_w[2*tid] + s_w[2*tid + 1]);
        return;
    }
    {
        __shared__ float s_bv[EE];
        int base = (bi - 585) * 32;
        int warp = tid >> 5, lane = tid & 31;
        if (tid < EE) s_bv[tid] = b_qkv[2*EE + tid];
        __syncthreads();
        #pragma unroll
        for (int q = 0; q < 4; q++) {
            int f = base + warp * 4 + q;
            float acc = warp_dot256(w_out + (size_t)f * EE, s_bv, lane);
            if (lane == 0) g_bias2[f] = acc + b_out[f];
        }
    }
}

// ---------------- kernel: attention -> xbar ----------------
__global__ __launch_bounds__(1024) void attn_kernel(const float* __restrict__ x,
                            const int* __restrict__ real_rows,
                            const float* __restrict__ cls) {
    __shared__ __align__(16) float s_u[HH*EE];
    __shared__ __align__(16) float s_sc[HH][SS];
    __shared__ __align__(16) float s_cls[EE];
    __shared__ __align__(16) float s_part[8][HH][EE];
    __shared__ float s_cb[HH];

    int bc  = blockIdx.x;
    int b   = bc >> 5;
    int tid = threadIdx.x;
    int warp = tid >> 5, lane = tid & 31;

    s_u[tid] = g_u[tid];
    if (tid < EE) s_cls[tid] = cls[tid];
    if (tid < HH) s_cb[tid] = g_cb[tid];
    __syncthreads();

    int nk = real_rows[b] + 1;
    const float* xbase = x + (size_t)bc * RR * EE;

    {
        int pos = warp;
        bool have = pos < nk;
        float4 v0, v1;
        if (have) {
            const float* row = (pos == 0) ? s_cls : (xbase + (size_t)(pos - 1) * EE);
            v0 = *(const float4*)(row + lane*4);
            v1 = *(const float4*)(row + 128 + lane*4);
        }
        while (have) {
            int npos = pos + 32;
            bool nh = npos < nk;
            float4 n0, n1;
            if (nh) {
                const float* nrow = xbase + (size_t)(npos - 1) * EE;
                n0 = *(const float4*)(nrow + lane*4);
                n1 = *(const float4*)(nrow + 128 + lane*4);
            }
            float acc[HH];
            #pragma unroll
            for (int h = 0; h < HH; h++) {
                float4 u0 = *(const float4*)(s_u + h*EE + lane*4);
                float4 u1 = *(const float4*)(s_u + h*EE + 128 + lane*4);
                acc[h] = v0.x*u0.x + v0.y*u0.y + v0.z*u0.z + v0.w*u0.w
                       + v1.x*u1.x + v1.y*u1.y + v1.z*u1.z + v1.w*u1.w;
            }
            #pragma unroll
            for (int o = 16; o; o >>= 1) {
                #pragma unroll
                for (int h = 0; h < HH; h++)
                    acc[h] += __shfl_xor_sync(0xffffffffu, acc[h], o);
            }
            if (lane == 0) {
                #pragma unroll
                for (int h = 0; h < HH; h++) s_sc[h][pos] = acc[h] + s_cb[h];
            }
            pos = npos; have = nh; v0 = n0; v1 = n1;
        }
    }
    __syncthreads();

    if (warp < HH) {
        int h = warp;
        float m = -3.0e38f;
        for (int p = lane; p < nk; p += 32) m = fmaxf(m, s_sc[h][p]);
        #pragma unroll
        for (int o = 16; o; o >>= 1) m = fmaxf(m, __shfl_xor_sync(0xffffffffu, m, o));
        float sum = 0.f;
        for (int p = lane; p < nk; p += 32) {
            float ev = __expf(s_sc[h][p] - m);
            s_sc[h][p] = ev;
            sum += ev;
        }
        #pragma unroll
        for (int o = 16; o; o >>= 1) sum += __shfl_xor_sync(0xffffffffu, sum, o);
        float inv = 1.f / sum;
        for (int p = lane; p < nk; p += 32) s_sc[h][p] *= inv;
    }
    __syncthreads();

    int pg = tid >> 7, ec = tid & 127;
    float2 a[HH];
    #pragma unroll
    for (int h = 0; h < HH; h++) a[h] = make_float2(0.f, 0.f);
    #pragma unroll 8
    for (int pos = pg; pos < nk; pos += 8) {
        float2 xv = (pos == 0) ? *(const float2*)(s_cls + ec*2)
                               : *(const float2*)(xbase + (size_t)(pos - 1) * EE + ec*2);
        #pragma unroll
        for (int h = 0; h < HH; h++) {
            float w = s_sc[h][pos];
            a[h].x += w * xv.x; a[h].y += w * xv.y;
        }
    }
    #pragma unroll
    for (int h = 0; h < HH; h++)
        *(float2*)&s_part[pg][h][ec*2] = a[h];
    __syncthreads();

    int h2 = tid >> 8, e2 = tid & 255;
    float s = 0.f;
    #pragma unroll
    for (int g = 0; g < 8; g++) s += s_part[g][h2][e2];
    g_xbar[(size_t)bc * HID + tid] = s;
}

// ---------------- kernel: mha partial GEMM + fused LN (last block) ----------------
__global__ __launch_bounds__(256, 4) void mha_part_kernel(const float* __restrict__ ln_g,
                                                          const float* __restrict__ ln_b) {
    __shared__ __align__(16) float s_xbT[64][8];
    __shared__ __align__(16) float s_buf[8320];   // weights 2x4096 | s_acc[4][8][260]
    __shared__ float s8[8];
    __shared__ int s_last;
    int t0 = blockIdx.x * TOK, slice = blockIdx.y;
    int tid = threadIdx.x;
    int fc = tid & 63, jg = tid >> 6;

    const float4* Wg = (const float4*)g_M2T + (size_t)(slice*64) * 64;

    #pragma unroll
    for (int r = 0; r < 4; r++) {
        int idx = r*256 + tid;
        cp_async16(&s_buf[idx*4], Wg + idx);
    }
    cp_commit();

    #pragma unroll
    for (int r = 0; r < 2; r++) {
        int idx = r*256 + tid;
        int t = idx >> 6, j = idx & 63;
        s_xbT[j][t] = g_xbar[(size_t)(t0 + t) * HID + slice*64 + j];
    }

    float4 a[TOK];
    #pragma unroll
    for (int tt = 0; tt < TOK; tt++) a[tt] = make_float4(0.f,0.f,0.f,0.f);

    #pragma unroll
    for (int c = 0; c < 4; c++) {
        if (c < 3) {
            const float4* src = Wg + (c+1)*1024;
            float* dst = &s_buf[((c+1)&1)*4096];
            #pragma unroll
            for (int r = 0; r < 4; r++) {
                int idx = r*256 + tid;
                cp_async16(dst + idx*4, src + idx);
            }
            cp_commit();
            cp_wait1();
        } else {
            cp_wait0();
        }
        __syncthreads();
        const float* wb = &s_buf[(c&1)*4096];
        #pragma unroll
        for (int jl = 0; jl < 4; jl++) {
            int j = jg*4 + jl;
            float4 m  = *(const float4*)&wb[(j*64 + fc)*4];
            float4 tA = *(const float4*)&s_xbT[c*16 + j][0];
            float4 tB = *(const float4*)&s_xbT[c*16 + j][4];
            ACC8(m, tA, tB);
        }
        __syncthreads();
    }

    float* s_acc = s_buf;
    #pragma unroll
    for (int tt = 0; tt < TOK; tt++)
        *(float4*)&s_acc[(jg*TOK + tt)*260 + fc*4] = a[tt];
    __syncthreads();
    int f = tid;
    #pragma unroll
    for (int tt = 0; tt < TOK; tt++) {
        float s = s_acc[(0*TOK+tt)*260 + f] + s_acc[(1*TOK+tt)*260 + f]
                + s_acc[(2*TOK+tt)*260 + f] + s_acc[(3*TOK+tt)*260 + f];
        g_part[((size_t)slice * NBC + t0 + tt) * EE + f] = s;
    }

    // ---- fused LayerNorm: last block for this token group ----
    __syncthreads();
    if (tid == 0) {
        __threadfence();
        unsigned old = atomicAdd(&g_cnt1[blockIdx.x], 1u);
        s_last = (old == NSL - 1);
    }
    __syncthreads();
    if (!s_last) return;
    __threadfence();
    float lg = ln_g[f], lb = ln_b[f], bias = g_bias2[f];
    #pragma unroll
    for (int tt = 0; tt < TOK; tt++) {
        int t = t0 + tt;
        float v = bias;
        #pragma unroll
        for (int sl = 0; sl < NSL; sl++)
            v += g_part[((size_t)sl * NBC + t) * EE + f];
        float mu = blk_sum256(v, s8, tid) * (1.f/EE);
        float d = v - mu;
        float var = blk_sum256(d*d, s8, tid) * (1.f/EE);
        g_ln[(size_t)t * EE + f] = d * rsqrtf(var + LN_EPS) * lg + lb;
    }
    if (tid == 0) g_cnt1[blockIdx.x] = 0;   // reset for next graph replay
}

// ---------------- kernel: FFN hidden ----------------
__global__ __launch_bounds__(256, 4) void ffn1_kernel(const float* __restrict__ b1) {
    __shared__ __align__(16) float s_lnT[EE][8];
    __shared__ __align__(16) float s_buf[8704];   // weights 2x(64x68) | s_acc[16][8][68]
    int t0 = blockIdx.x * TOK, slice = blockIdx.y;
    int tid = threadIdx.x;
    int jc = tid & 15, eg = tid >> 4;

    const float4* Wg = (const float4*)g_W1T + slice*16;

    #pragma unroll
    for (int r = 0; r < 4; r++) {
        int idx = r*256 + tid;
        int row = idx >> 4, q = idx & 15;
        cp_async16(&s_buf[row*68 + q*4], Wg + (size_t)row * 256 + q);
    }
    cp_commit();

    #pragma unroll
    for (int r = 0; r < 8; r++) {
        int idx = r*256 + tid;
        int t = idx >> 8, e = idx & 255;
        s_lnT[e][t] = g_ln[(size_t)(t0 + t) * EE + e];
    }

    float4 a[TOK];
    #pragma unroll
    for (int tt = 0; tt < TOK; tt++) a[tt] = make_float4(0.f,0.f,0.f,0.f);

    #pragma unroll
    for (int c = 0; c < 4; c++) {
        if (c < 3) {
            const float4* src = Wg + (size_t)(c+1) * 64 * 256;
            float* dst = &s_buf[((c+1)&1)*4352];
            #pragma unroll
            for (int r = 0; r < 4; r++) {
                int idx = r*256 + tid;
                int row = idx >> 4, q = idx & 15;
                cp_async16(dst + row*68 + q*4, src + (size_t)row * 256 + q);
            }
            cp_commit();
            cp_wait1();
        } else {
            cp_wait0();
        }
        __syncthreads();
        const float* wb = &s_buf[(c&1)*4352];
        #pragma unroll
        for (int i = 0; i < 4; i++) {
            int el = eg*4 + i;
            float4 m  = *(const float4*)&wb[el*68 + jc*4];
            float4 tA = *(const float4*)&s_lnT[c*64 + el][0];
            float4 tB = *(const float4*)&s_lnT[c*64 + el][4];
            ACC8(m, tA, tB);
        }
        __syncthreads();
    }

    float* s_acc = s_buf;
    #pragma unroll
    for (int tt = 0; tt < TOK; tt++)
        *(float4*)&s_acc[(eg*TOK + tt)*68 + jc*4] = a[tt];
    __syncthreads();

    #pragma unroll
    for (int r = 0; r < 2; r++) {
        int idx = r*256 + tid;
        int tt = idx >> 6, jj = idx & 63;
        float s = 0.f;
        #pragma unroll
        for (int g = 0; g < 16; g++) s += s_acc[(g*TOK + tt)*68 + jj];
        g_hid[(size_t)(t0 + tt) * HID + slice*64 + jj] = fmaxf(s + b1[slice*64 + jj], 0.f);
    }
}

// ---------------- kernel: FFN out partial GEMM + fused residual/mask (last block) ----------------
__global__ __launch_bounds__(256, 4) void ffn2_kernel(const float* __restrict__ b2,
                                                      const int* __restrict__ real_cols,
                                                      float* __restrict__ out) {
    __shared__ __align__(16) float s_hT[64][8];
    __shared__ __align__(16) float s_buf[8320];
    __shared__ int s_last;
    int t0 = blockIdx.x * TOK, slice = blockIdx.y;
    int tid = threadIdx.x;
    int fc = tid & 63, jg = tid >> 6;

    const float4* Wg = (const float4*)g_W2T + (size_t)(slice*64) * 64;

    #pragma unroll
    for (int r = 0; r < 4; r++) {
        int idx = r*256 + tid;
        cp_async16(&s_buf[idx*4], Wg + idx);
    }
    cp_commit();

    #pragma unroll
    for (int r = 0; r < 2; r++) {
        int idx = r*256 + tid;
        int t = idx >> 6, j = idx & 63;
        s_hT[j][t] = g_hid[(size_t)(t0 + t) * HID + slice*64 + j];
    }

    float4 a[TOK];
    #pragma unroll
    for (int tt = 0; tt < TOK; tt++) a[tt] = make_float4(0.f,0.f,0.f,0.f);

    #pragma unroll
    for (int c = 0; c < 4; c++) {
        if (c < 3) {
            const float4* src = Wg + (c+1)*1024;
            float* dst = &s_buf[((c+1)&1)*4096];
            #pragma unroll
            for (int r = 0; r < 4; r++) {
                int idx = r*256 + tid;
                cp_async16(dst + idx*4, src + idx);
            }
            cp_commit();
            cp_wait1();
        } else {
            cp_wait0();
        }
        __syncthreads();
        const float* wb = &s_buf[(c&1)*4096];
        #pragma unroll
        for (int jl = 0; jl < 4; jl++) {
            int j = jg*4 + jl;
            float4 m  = *(const float4*)&wb[(j*64 + fc)*4];
            float4 tA = *(const float4*)&s_hT[c*16 + j][0];
            float4 tB = *(const float4*)&s_hT[c*16 + j][4];
            ACC8(m, tA, tB);
        }
        __syncthreads();
    }

    float* s_acc = s_buf;
    #pragma unroll
    for (int tt = 0; tt < TOK; tt++)
        *(float4*)&s_acc[(jg*TOK + tt)*260 + fc*4] = a[tt];
    __syncthreads();
    int f = tid;
    #pragma unroll
    for (int tt = 0; tt < TOK; tt++) {
        float s = s_acc[(0*TOK+tt)*260 + f] + s_acc[(1*TOK+tt)*260 + f]
                + s_acc[(2*TOK+tt)*260 + f] + s_acc[(3*TOK+tt)*260 + f];
        g_part2[((size_t)slice * NBC + t0 + tt) * EE + f] = s;
    }

    // ---- fused final reduce + residual + mask: last block ----
    __syncthreads();
    if (tid == 0) {
        __threadfence();
        unsigned old = atomicAdd(&g_cnt2[blockIdx.x], 1u);
        s_last = (old == NSL - 1);
    }
    __syncthreads();
    if (!s_last) return;
    __threadfence();
    float bf = b2[f];
    #pragma unroll
    for (int tt = 0; tt < TOK; tt++) {
        int t = t0 + tt;
        int bidx = t >> 5, cidx = t & 31;
        bool valid = cidx < real_cols[bidx];
        float s = bf + g_ln[(size_t)t * EE + f];
        #pragma unroll
        for (int sl = 0; sl < NSL; sl++)
            s += g_part2[((size_t)sl * NBC + t) * EE + f];
        out[(size_t)t * EE + f] = valid ? s : 0.f;
    }
    if (tid == 0) g_cnt2[blockIdx.x] = 0;   // reset for next graph replay
}

// ---------------- launch ----------------
extern "C" void kernel_launch(void* const* d_in, const int* in_sizes, int n_in,
                              void* d_out, int out_size) {
    const float* x         = (const float*)d_in[0];
    const int*   real_cols = (const int*)  d_in[1];
    const int*   real_rows = (const int*)  d_in[2];
    const float* cls       = (const float*)d_in[3];
    const float* w_qkv     = (const float*)d_in[4];
    const float* b_qkv     = (const float*)d_in[5];
    const float* w_out     = (const float*)d_in[6];
    const float* b_out     = (const float*)d_in[7];
    const float* ln_g      = (const float*)d_in[8];
    const float* ln_b      = (const float*)d_in[9];
    const float* w1        = (const float*)d_in[10];
    const float* b1        = (const float*)d_in[11];
    const float* w2        = (const float*)d_in[12];
    const float* b2        = (const float*)d_in[13];
    float* out = (float*)d_out;

    setup_kernel<<<593, 256>>>(cls, w_qkv, b_qkv, w_out, b_out, w1, w2);
    attn_kernel<<<NBC, 1024>>>(x, real_rows, cls);
    mha_part_kernel<<<dim3(NBC/TOK, NSL), 256>>>(ln_g, ln_b);
    ffn1_kernel<<<dim3(NBC/TOK, NSL), 256>>>(b1);
    ffn2_kernel<<<dim3(NBC/TOK, NSL), 256>>>(b2, real_cols, out);
}

// round 9
// speedup vs baseline: 1.0732x; 1.0732x over previous
#include <cuda_runtime.h>
#include <cuda_bf16.h>
#include <cstdint>

#define EE    256
#define HH    4
#define DH    64
#define BB    8
#define CC    32
#define RR    255
#define SS    256
#define HID   1024
#define NBC   (BB*CC)
#define TOK   16
#define NSL   16           // j-split slices (64 j each)
#define LN_EPS 1e-5f

// ---------------- device scratch ----------------
__device__ __align__(16) float g_q0[EE];
__device__ __align__(16) float g_u[HH*EE];
__device__ __align__(16) float g_cb[HH];
__device__ __align__(16) float g_bias2[EE];
__device__ __align__(16) float g_M2T[HID*EE];      // [j][f]
__device__ __align__(16) float g_W1T[EE*HID];      // [e][j]
__device__ __align__(16) float g_W2T[HID*EE];      // [j][f]
__device__ __align__(16) float g_xbar[NBC*HID];
__device__ __align__(16) float g_ln[NBC*EE];
__device__ __align__(16) float g_hid[NBC*HID];
__device__ __align__(16) float g_part[NSL*NBC*EE];   // 4MB
__device__ __align__(16) float g_part2[NSL*NBC*EE];  // 4MB

// ---------------- cp.async helpers ----------------
__device__ __forceinline__ void cp_async16(float* sdst, const float4* gsrc) {
    unsigned sa = (unsigned)__cvta_generic_to_shared(sdst);
    asm volatile("cp.async.ca.shared.global [%0], [%1], 16;" :: "r"(sa), "l"(gsrc));
}
__device__ __forceinline__ void cp_commit() { asm volatile("cp.async.commit_group;"); }
__device__ __forceinline__ void cp_wait1()  { asm volatile("cp.async.wait_group 1;"); }
__device__ __forceinline__ void cp_wait0()  { asm volatile("cp.async.wait_group 0;"); }

__device__ __forceinline__ float warp_dot256(const float* __restrict__ row,
                                             const float* __restrict__ svec, int lane) {
    float4 w0 = *(const float4*)(row + lane*4);
    float4 w1 = *(const float4*)(row + 128 + lane*4);
    float4 c0 = *(const float4*)(svec + lane*4);
    float4 c1 = *(const float4*)(svec + 128 + lane*4);
    float acc = w0.x*c0.x + w0.y*c0.y + w0.z*c0.z + w0.w*c0.w
              + w1.x*c1.x + w1.y*c1.y + w1.z*c1.z + w1.w*c1.w;
    #pragma unroll
    for (int o = 16; o; o >>= 1) acc += __shfl_xor_sync(0xffffffffu, acc, o);
    return acc;
}

// ---------------- kernel: q0 = W_q.cls + b_q ----------------
__global__ __launch_bounds__(256) void prep1_kernel(const float* __restrict__ cls,
                              const float* __restrict__ w_qkv,
                              const float* __restrict__ b_qkv) {
    __shared__ float s_cls[EE];
    int tid = threadIdx.x, warp = tid >> 5, lane = tid & 31;
    if (tid < EE) s_cls[tid] = cls[tid];
    __syncthreads();
    #pragma unroll
    for (int q = 0; q < 4; q++) {
        int f = blockIdx.x * 32 + warp * 4 + q;
        float acc = warp_dot256(w_qkv + (size_t)f * EE, s_cls, lane);
        if (lane == 0) g_q0[f] = acc + b_qkv[f];
    }
}

// ---------------- kernel: setup ----------------
// [0,64): M2T | [64,576): transposes | [576,584): u | 584: cb | [585,593): bias2
__global__ __launch_bounds__(256) void setup_kernel(const float* __restrict__ w_qkv,
                              const float* __restrict__ b_qkv,
                              const float* __restrict__ w_out,
                              const float* __restrict__ b_out,
                              const float* __restrict__ w1,
                              const float* __restrict__ w2) {
    int bi = blockIdx.x;
    int tid = threadIdx.x;

    if (bi < 64) {
        __shared__ float sa[64][64];
        __shared__ float sb[64][65];
        int h = bi >> 4, e0 = ((bi >> 2) & 3) * 64, f0 = (bi & 3) * 64;
        for (int i = tid; i < 4096; i += 256) {
            int d = i >> 6, el = i & 63;
            sa[d][el] = w_qkv[(size_t)(2*EE + h*64 + d) * EE + e0 + el];
        }
        for (int i = tid; i < 4096; i += 256) {
            int fl = i >> 6, d = i & 63;
            sb[fl][d] = w_out[(size_t)(f0 + fl) * EE + h*64 + d];
        }
        __syncthreads();
        int tx = tid & 15, ty = tid >> 4;
        float acc[4][4] = {};
        #pragma unroll 4
        for (int d = 0; d < 64; d++) {
            float av[4], bv[4];
            #pragma unroll
            for (int i = 0; i < 4; i++) av[i] = sa[d][ty*4 + i];
            #pragma unroll
            for (int i = 0; i < 4; i++) bv[i] = sb[tx*4 + i][d];
            #pragma unroll
            for (int i = 0; i < 4; i++)
                #pragma unroll
                for (int j = 0; j < 4; j++) acc[i][j] += av[i] * bv[j];
        }
        #pragma unroll
        for (int i = 0; i < 4; i++)
            *(float4*)&g_M2T[(size_t)(h*256 + e0 + ty*4 + i) * EE + f0 + tx*4] = *(float4*)acc[i];
        return;
    }
    if (bi < 576) {
        __shared__ float s[32][33];
        int a = bi - 64;
        const float* src; float* dst; int rows, cols, bx, by;
        if (a < 256) {
            src = w1; dst = g_W1T; rows = HID; cols = EE;
            bx = (a & 7) * 32; by = (a >> 3) * 32;
        } else {
            a -= 256;
            src = w2; dst = g_W2T; rows = EE; cols = HID;
            bx = (a & 31) * 32; by = (a >> 5) * 32;
        }
        int tx = tid & 31, ty = tid >> 5;
        #pragma unroll
        for (int r = 0; r < 4; r++)
            s[ty + r*8][tx] = src[(size_t)(by + ty + r*8) * cols + bx + tx];
        __syncthreads();
        #pragma unroll
        for (int r = 0; r < 4; r++)
            dst[(size_t)(bx + ty + r*8) * rows + by + tx] = s[tx][ty + r*8];
        return;
    }
    if (bi < 584) {
        __shared__ float s_q[DH];
        __shared__ float s_p[2][128];
        int k = bi - 576;
        int h = k >> 1, e0 = (k & 1) * 128;
        if (tid < DH) s_q[tid] = g_q0[h*DH + tid];
        __syncthreads();
        int dg = tid >> 7, e = e0 + (tid & 127);
        float acc = 0.f;
        #pragma unroll 8
        for (int i = 0; i < 32; i++) {
            int d = dg*32 + i;
            acc += s_q[d] * w_qkv[(size_t)(EE + h*DH + d) * EE + e];
        }
        s_p[dg][tid & 127] = acc;
        __syncthreads();
        if (tid < 128)
            g_u[h*EE + e0 + tid] = 0.125f * (s_p[0][tid] + s_p[1][tid]);
        return;
    }
    if (bi == 584) {
        __shared__ float s_w[8];
        int h = tid >> 6, d = tid & 63;
        float v = g_q0[h*DH + d] * b_qkv[EE + h*DH + d];
        #pragma unroll
        for (int o = 16; o; o >>= 1) v += __shfl_xor_sync(0xffffffffu, v, o);
        if ((tid & 31) == 0) s_w[tid >> 5] = v;
        __syncthreads();
        if (tid < HH) g_cb[tid] = 0.125f * (s_w[2*tid] + s_w[2*tid + 1]);
        return;
    }
    {
        __shared__ float s_bv[EE];
        int base = (bi - 585) * 32;
        int warp = tid >> 5, lane = tid & 31;
        if (tid < EE) s_bv[tid] = b_qkv[2*EE + tid];
        __syncthreads();
        #pragma unroll
        for (int q = 0; q < 4; q++) {
            int f = base + warp * 4 + q;
            float acc = warp_dot256(w_out + (size_t)f * EE, s_bv, lane);
            if (lane == 0) g_bias2[f] = acc + b_out[f];
        }
    }
}

// ---------------- kernel: attention -> xbar ----------------
__global__ __launch_bounds__(1024) void attn_kernel(const float* __restrict__ x,
                            const int* __restrict__ real_rows,
                            const float* __restrict__ cls) {
    __shared__ __align__(16) float s_u[HH*EE];
    __shared__ __align__(16) float s_sc[HH][SS];
    __shared__ __align__(16) float s_cls[EE];
    __shared__ __align__(16) float s_part[8][HH][EE];
    __shared__ float s_cb[HH];

    int bc  = blockIdx.x;
    int b   = bc >> 5;
    int tid = threadIdx.x;
    int warp = tid >> 5, lane = tid & 31;

    s_u[tid] = g_u[tid];
    if (tid < EE) s_cls[tid] = cls[tid];
    if (tid < HH) s_cb[tid] = g_cb[tid];
    __syncthreads();

    int nk = real_rows[b] + 1;
    const float* xbase = x + (size_t)bc * RR * EE;

    {
        int pos = warp;
        bool have = pos < nk;
        float4 v0, v1;
        if (have) {
            const float* row = (pos == 0) ? s_cls : (xbase + (size_t)(pos - 1) * EE);
            v0 = *(const float4*)(row + lane*4);
            v1 = *(const float4*)(row + 128 + lane*4);
        }
        while (have) {
            int npos = pos + 32;
            bool nh = npos < nk;
            float4 n0, n1;
            if (nh) {
                const float* nrow = xbase + (size_t)(npos - 1) * EE;
                n0 = *(const float4*)(nrow + lane*4);
                n1 = *(const float4*)(nrow + 128 + lane*4);
            }
            float acc[HH];
            #pragma unroll
            for (int h = 0; h < HH; h++) {
                float4 u0 = *(const float4*)(s_u + h*EE + lane*4);
                float4 u1 = *(const float4*)(s_u + h*EE + 128 + lane*4);
                acc[h] = v0.x*u0.x + v0.y*u0.y + v0.z*u0.z + v0.w*u0.w
                       + v1.x*u1.x + v1.y*u1.y + v1.z*u1.z + v1.w*u1.w;
            }
            #pragma unroll
            for (int o = 16; o; o >>= 1) {
                #pragma unroll
                for (int h = 0; h < HH; h++)
                    acc[h] += __shfl_xor_sync(0xffffffffu, acc[h], o);
            }
            if (lane == 0) {
                #pragma unroll
                for (int h = 0; h < HH; h++) s_sc[h][pos] = acc[h] + s_cb[h];
            }
            pos = npos; have = nh; v0 = n0; v1 = n1;
        }
    }
    __syncthreads();

    if (warp < HH) {
        int h = warp;
        float m = -3.0e38f;
        for (int p = lane; p < nk; p += 32) m = fmaxf(m, s_sc[h][p]);
        #pragma unroll
        for (int o = 16; o; o >>= 1) m = fmaxf(m, __shfl_xor_sync(0xffffffffu, m, o));
        float sum = 0.f;
        for (int p = lane; p < nk; p += 32) {
            float ev = __expf(s_sc[h][p] - m);
            s_sc[h][p] = ev;
            sum += ev;
        }
        #pragma unroll
        for (int o = 16; o; o >>= 1) sum += __shfl_xor_sync(0xffffffffu, sum, o);
        float inv = 1.f / sum;
        for (int p = lane; p < nk; p += 32) s_sc[h][p] *= inv;
    }
    __syncthreads();

    int pg = tid >> 7, ec = tid & 127;
    float2 a[HH];
    #pragma unroll
    for (int h = 0; h < HH; h++) a[h] = make_float2(0.f, 0.f);
    #pragma unroll 8
    for (int pos = pg; pos < nk; pos += 8) {
        float2 xv = (pos == 0) ? *(const float2*)(s_cls + ec*2)
                               : *(const float2*)(xbase + (size_t)(pos - 1) * EE + ec*2);
        #pragma unroll
        for (int h = 0; h < HH; h++) {
            float w = s_sc[h][pos];
            a[h].x += w * xv.x; a[h].y += w * xv.y;
        }
    }
    #pragma unroll
    for (int h = 0; h < HH; h++)
        *(float2*)&s_part[pg][h][ec*2] = a[h];
    __syncthreads();

    int h2 = tid >> 8, e2 = tid & 255;
    float s = 0.f;
    #pragma unroll
    for (int g = 0; g < 8; g++) s += s_part[g][h2][e2];
    g_xbar[(size_t)bc * HID + tid] = s;
}

// ---------------- kernel: mha partial GEMM, TOK=16, one f per thread ----------------
__global__ __launch_bounds__(256) void mha_part_kernel() {
    __shared__ __align__(16) float s_xbT[64][16];    // 4KB [j][t]
    __shared__ __align__(16) float s_w[2][4096];     // 32KB double buffer
    int t0 = blockIdx.x * TOK, slice = blockIdx.y;
    int tid = threadIdx.x;
    int f = tid;

    const float4* Wg = (const float4*)g_M2T + (size_t)(slice*64) * 64;

    // prefetch chunk 0 (j rows 0..15 of tile)
    #pragma unroll
    for (int r = 0; r < 4; r++) {
        int idx = r*256 + tid;
        cp_async16(&s_w[0][idx*4], Wg + idx);
    }
    cp_commit();

    // stage xbar transposed: [j][t]
    #pragma unroll
    for (int r = 0; r < 4; r++) {
        int idx = r*256 + tid;
        int t = idx >> 6, j = idx & 63;
        s_xbT[j][t] = g_xbar[(size_t)(t0 + t) * HID + slice*64 + j];
    }

    float acc[TOK];
    #pragma unroll
    for (int t = 0; t < TOK; t++) acc[t] = 0.f;

    #pragma unroll
    for (int c = 0; c < 4; c++) {
        if (c < 3) {
            #pragma unroll
            for (int r = 0; r < 4; r++) {
                int idx = r*256 + tid;
                cp_async16(&s_w[(c+1)&1][idx*4], Wg + (c+1)*1024 + idx);
            }
            cp_commit();
            cp_wait1();
        } else {
            cp_wait0();
        }
        __syncthreads();
        const float* wb = s_w[c&1];
        #pragma unroll
        for (int jl = 0; jl < 16; jl++) {
            int j = c*16 + jl;
            float w = wb[jl*256 + f];
            float4 x0 = *(const float4*)&s_xbT[j][0];
            float4 x1 = *(const float4*)&s_xbT[j][4];
            float4 x2 = *(const float4*)&s_xbT[j][8];
            float4 x3 = *(const float4*)&s_xbT[j][12];
            acc[0]  += w*x0.x; acc[1]  += w*x0.y; acc[2]  += w*x0.z; acc[3]  += w*x0.w;
            acc[4]  += w*x1.x; acc[5]  += w*x1.y; acc[6]  += w*x1.z; acc[7]  += w*x1.w;
            acc[8]  += w*x2.x; acc[9]  += w*x2.y; acc[10] += w*x2.z; acc[11] += w*x2.w;
            acc[12] += w*x3.x; acc[13] += w*x3.y; acc[14] += w*x3.z; acc[15] += w*x3.w;
        }
        __syncthreads();
    }

    #pragma unroll
    for (int t = 0; t < TOK; t++)
        g_part[((size_t)slice * NBC + t0 + t) * EE + f] = acc[t];
}

// ---------------- block reduce ----------------
__device__ __forceinline__ float blk_sum256(float v, volatile float* s8, int tid) {
    #pragma unroll
    for (int o = 16; o; o >>= 1) v += __shfl_xor_sync(0xffffffffu, v, o);
    if ((tid & 31) == 0) s8[tid >> 5] = v;
    __syncthreads();
    float r = s8[0]+s8[1]+s8[2]+s8[3]+s8[4]+s8[5]+s8[6]+s8[7];
    __syncthreads();
    return r;
}

// ---------------- kernel: LN reduce (block per token) ----------------
__global__ __launch_bounds__(256) void lnred_kernel(const float* __restrict__ ln_g,
                             const float* __restrict__ ln_b) {
    __shared__ float s8[8];
    int t = blockIdx.x;
    int tid = threadIdx.x;
    float v = g_bias2[tid];
    #pragma unroll
    for (int sl = 0; sl < NSL; sl++)
        v += g_part[((size_t)sl * NBC + t) * EE + tid];
    float mu = blk_sum256(v, s8, tid) * (1.f/EE);
    float d = v - mu;
    float var = blk_sum256(d*d, s8, tid) * (1.f/EE);
    g_ln[(size_t)t * EE + tid] = d * rsqrtf(var + LN_EPS) * ln_g[tid] + ln_b[tid];
}

// ---------------- kernel: FFN hidden, TOK=16, full e-reduction per thread ----------------
__global__ __launch_bounds__(256) void ffn1_kernel(const float* __restrict__ b1) {
    __shared__ __align__(16) float s_lnT[EE][20];    // 20KB [e][t] (pad 20, 16B-aligned groups)
    __shared__ __align__(16) float s_w[2][2048];     // 16KB double buffer (32 e x 64 j)
    int t0 = blockIdx.x * TOK, slice = blockIdx.y;
    int tid = threadIdx.x;
    int j = tid & 63, tg = tid >> 6;   // tokens tg*4 .. tg*4+3

    const float4* Wg = (const float4*)g_W1T + slice*16;   // + e*256 quads per row

    // prefetch chunk 0: e rows 0..31, 16 quads each
    #pragma unroll
    for (int r = 0; r < 2; r++) {
        int idx = r*256 + tid;
        int row = idx >> 4, q = idx & 15;
        cp_async16(&s_w[0][(row*16 + q)*4], Wg + (size_t)row * 256 + q);
    }
    cp_commit();

    // stage ln transposed: [e][t]
    #pragma unroll
    for (int r = 0; r < 16; r++) {
        int idx = r*256 + tid;
        int t = idx >> 8, e = idx & 255;
        s_lnT[e][t] = g_ln[(size_t)(t0 + t) * EE + e];
    }

    float acc[4] = {0.f, 0.f, 0.f, 0.f};

    #pragma unroll
    for (int c = 0; c < 8; c++) {
        if (c < 7) {
            #pragma unroll
            for (int r = 0; r < 2; r++) {
                int idx = r*256 + tid;
                int row = idx >> 4, q = idx & 15;
                cp_async16(&s_w[(c+1)&1][(row*16 + q)*4],
                           Wg + (size_t)((c+1)*32 + row) * 256 + q);
            }
            cp_commit();
            cp_wait1();
        } else {
            cp_wait0();
        }
        __syncthreads();
        const float* wb = s_w[c&1];
        #pragma unroll
        for (int el = 0; el < 32; el++) {
            int e = c*32 + el;
            float w = wb[el*64 + j];
            float4 lv = *(const float4*)&s_lnT[e][tg*4];
            acc[0] += w*lv.x; acc[1] += w*lv.y; acc[2] += w*lv.z; acc[3] += w*lv.w;
        }
        __syncthreads();
    }

    float bj = b1[slice*64 + j];
    #pragma unroll
    for (int k = 0; k < 4; k++)
        g_hid[(size_t)(t0 + tg*4 + k) * HID + slice*64 + j] = fmaxf(acc[k] + bj, 0.f);
}

// ---------------- kernel: FFN out partial GEMM, TOK=16 ----------------
__global__ __launch_bounds__(256) void ffn2_kernel() {
    __shared__ __align__(16) float s_hT[64][16];
    __shared__ __align__(16) float s_w[2][4096];
    int t0 = blockIdx.x * TOK, slice = blockIdx.y;
    int tid = threadIdx.x;
    int f = tid;

    const float4* Wg = (const float4*)g_W2T + (size_t)(slice*64) * 64;

    #pragma unroll
    for (int r = 0; r < 4; r++) {
        int idx = r*256 + tid;
        cp_async16(&s_w[0][idx*4], Wg + idx);
    }
    cp_commit();

    #pragma unroll
    for (int r = 0; r < 4; r++) {
        int idx = r*256 + tid;
        int t = idx >> 6, j = idx & 63;
        s_hT[j][t] = g_hid[(size_t)(t0 + t) * HID + slice*64 + j];
    }

    float acc[TOK];
    #pragma unroll
    for (int t = 0; t < TOK; t++) acc[t] = 0.f;

    #pragma unroll
    for (int c = 0; c < 4; c++) {
        if (c < 3) {
            #pragma unroll
            for (int r = 0; r < 4; r++) {
                int idx = r*256 + tid;
                cp_async16(&s_w[(c+1)&1][idx*4], Wg + (c+1)*1024 + idx);
            }
            cp_commit();
            cp_wait1();
        } else {
            cp_wait0();
        }
        __syncthreads();
        const float* wb = s_w[c&1];
        #pragma unroll
        for (int jl = 0; jl < 16; jl++) {
            int j = c*16 + jl;
            float w = wb[jl*256 + f];
            float4 x0 = *(const float4*)&s_hT[j][0];
            float4 x1 = *(const float4*)&s_hT[j][4];
            float4 x2 = *(const float4*)&s_hT[j][8];
            float4 x3 = *(const float4*)&s_hT[j][12];
            acc[0]  += w*x0.x; acc[1]  += w*x0.y; acc[2]  += w*x0.z; acc[3]  += w*x0.w;
            acc[4]  += w*x1.x; acc[5]  += w*x1.y; acc[6]  += w*x1.z; acc[7]  += w*x1.w;
            acc[8]  += w*x2.x; acc[9]  += w*x2.y; acc[10] += w*x2.z; acc[11] += w*x2.w;
            acc[12] += w*x3.x; acc[13] += w*x3.y; acc[14] += w*x3.z; acc[15] += w*x3.w;
        }
        __syncthreads();
    }

    #pragma unroll
    for (int t = 0; t < TOK; t++)
        g_part2[((size_t)slice * NBC + t0 + t) * EE + f] = acc[t];
}

// ---------------- kernel: final reduce + residual + mask ----------------
__global__ __launch_bounds__(256) void outred_kernel(const float* __restrict__ b2,
                              const int* __restrict__ real_cols,
                              float* __restrict__ out) {
    int t = blockIdx.x;
    int tid = threadIdx.x;
    int bidx = t >> 5, cidx = t & 31;
    bool valid = cidx < real_cols[bidx];
    float s = b2[tid] + g_ln[(size_t)t * EE + tid];
    #pragma unroll
    for (int sl = 0; sl < NSL; sl++)
        s += g_part2[((size_t)sl * NBC + t) * EE + tid];
    out[(size_t)t * EE + tid] = valid ? s : 0.f;
}

// ---------------- launch ----------------
extern "C" void kernel_launch(void* const* d_in, const int* in_sizes, int n_in,
                              void* d_out, int out_size) {
    const float* x         = (const float*)d_in[0];
    const int*   real_cols = (const int*)  d_in[1];
    const int*   real_rows = (const int*)  d_in[2];
    const float* cls       = (const float*)d_in[3];
    const float* w_qkv     = (const float*)d_in[4];
    const float* b_qkv     = (const float*)d_in[5];
    const float* w_out     = (const float*)d_in[6];
    const float* b_out     = (const float*)d_in[7];
    const float* ln_g      = (const float*)d_in[8];
    const float* ln_b      = (const float*)d_in[9];
    const float* w1        = (const float*)d_in[10];
    const float* b1        = (const float*)d_in[11];
    const float* w2        = (const float*)d_in[12];
    const float* b2        = (const float*)d_in[13];
    float* out = (float*)d_out;

    prep1_kernel<<<8, 256>>>(cls, w_qkv, b_qkv);
    setup_kernel<<<593, 256>>>(w_qkv, b_qkv, w_out, b_out, w1, w2);
    attn_kernel<<<NBC, 1024>>>(x, real_rows, cls);
    mha_part_kernel<<<dim3(NBC/TOK, NSL), 256>>>();
    lnred_kernel<<<NBC, 256>>>(ln_g, ln_b);
    ffn1_kernel<<<dim3(NBC/TOK, NSL), 256>>>(b1);
    ffn2_kernel<<<dim3(NBC/TOK, NSL), 256>>>();
    outred_kernel<<<NBC, 256>>>(b2, real_cols, out);
}